// round 4
// baseline (speedup 1.0000x reference)
#include <cuda_runtime.h>
#include <cstdint>

// sbvr decode:
//   out[g*16 + l] = sum_s coeff_cache[coeff_idx[g]][s] * ((bvr[g][s] >> l) & 1)
// G = 4,194,304 groups, S = 4, L = 16.
//
// R3 -> R4: persistent software pipeline. R3 showed issue=34% with nothing
// saturated: every short-lived thread paid the idx->gather fill (~1500cyc)
// once for ~60 instrs of work. Now 1M threads each decode 16 quarter-groups
// in a rolled loop with a rotating depth-4 buffer:
//   idx+bvr prefetch distance 3 (covers ~1000cyc DRAM latency),
//   coeff gather  distance 1 (covers ~400cyc L2 latency).
// Fill paid once per thread; steady state is throughput-bound.

static constexpr unsigned QT_TOTAL = 16u * 1024u * 1024u;  // 4M groups * 4 quarters
static constexpr int      ITER     = 16;                   // quarter-groups per thread
static constexpr unsigned NTHREADS = QT_TOTAL / ITER;      // 1M
static constexpr unsigned STRIDE   = NTHREADS;             // quarter-index stride per iter
static constexpr int      BLOCK    = 256;
static constexpr int      DEPTH    = 4;                    // rotation buffer (power of 2)
static constexpr int      PF       = 3;                    // idx/bvr prefetch distance

// Pipe-balanced decode: lop3 with predicate output (ALU, AND+test in one op)
// feeding predicated add.f32 (FMA pipe). Exact fp32 -> rel_err 0.
__device__ __forceinline__ float4 decode_quarter(int4 w, float4 c, unsigned m0)
{
    float4 r;
    asm(
    "{\n\t"
    ".reg .pred q, p0, p1, p2, p3;\n\t"
    ".reg .b32  t, m1, m2, m3;\n\t"
    "setp.ne.u32 q, %4, %4;\n\t"
    "shl.b32 m1, %8, 1;\n\t"
    "shl.b32 m2, %8, 2;\n\t"
    "shl.b32 m3, %8, 3;\n\t"
    "lop3.or.b32 t|p0, %4, %8, %4, 0xC0, q;\n\t"
    "lop3.or.b32 t|p1, %5, %8, %5, 0xC0, q;\n\t"
    "lop3.or.b32 t|p2, %6, %8, %6, 0xC0, q;\n\t"
    "lop3.or.b32 t|p3, %7, %8, %7, 0xC0, q;\n\t"
    "selp.f32 %0, %9, 0f00000000, p0;\n\t"
    "@p1 add.rn.f32 %0, %0, %10;\n\t"
    "@p2 add.rn.f32 %0, %0, %11;\n\t"
    "@p3 add.rn.f32 %0, %0, %12;\n\t"
    "lop3.or.b32 t|p0, %4, m1, %4, 0xC0, q;\n\t"
    "lop3.or.b32 t|p1, %5, m1, %5, 0xC0, q;\n\t"
    "lop3.or.b32 t|p2, %6, m1, %6, 0xC0, q;\n\t"
    "lop3.or.b32 t|p3, %7, m1, %7, 0xC0, q;\n\t"
    "selp.f32 %1, %9, 0f00000000, p0;\n\t"
    "@p1 add.rn.f32 %1, %1, %10;\n\t"
    "@p2 add.rn.f32 %1, %1, %11;\n\t"
    "@p3 add.rn.f32 %1, %1, %12;\n\t"
    "lop3.or.b32 t|p0, %4, m2, %4, 0xC0, q;\n\t"
    "lop3.or.b32 t|p1, %5, m2, %5, 0xC0, q;\n\t"
    "lop3.or.b32 t|p2, %6, m2, %6, 0xC0, q;\n\t"
    "lop3.or.b32 t|p3, %7, m2, %7, 0xC0, q;\n\t"
    "selp.f32 %2, %9, 0f00000000, p0;\n\t"
    "@p1 add.rn.f32 %2, %2, %10;\n\t"
    "@p2 add.rn.f32 %2, %2, %11;\n\t"
    "@p3 add.rn.f32 %2, %2, %12;\n\t"
    "lop3.or.b32 t|p0, %4, m3, %4, 0xC0, q;\n\t"
    "lop3.or.b32 t|p1, %5, m3, %5, 0xC0, q;\n\t"
    "lop3.or.b32 t|p2, %6, m3, %6, 0xC0, q;\n\t"
    "lop3.or.b32 t|p3, %7, m3, %7, 0xC0, q;\n\t"
    "selp.f32 %3, %9, 0f00000000, p0;\n\t"
    "@p1 add.rn.f32 %3, %3, %10;\n\t"
    "@p2 add.rn.f32 %3, %3, %11;\n\t"
    "@p3 add.rn.f32 %3, %3, %12;\n\t"
    "}\n\t"
    : "=f"(r.x), "=f"(r.y), "=f"(r.z), "=f"(r.w)
    : "r"(w.x), "r"(w.y), "r"(w.z), "r"(w.w),
      "r"(m0),
      "f"(c.x), "f"(c.y), "f"(c.z), "f"(c.w));
    return r;
}

__global__ __launch_bounds__(BLOCK) void sbvr_kernel(
    const float4* __restrict__ coeff_cache,   // [65536] rows of 4 floats
    const int*    __restrict__ coeff_idx,     // [G]
    const int4*   __restrict__ bvr,           // [G]
    float4*       __restrict__ out)           // [4*G]
{
    unsigned t  = blockIdx.x * (unsigned)BLOCK + threadIdx.x;
    unsigned m0 = 1u << ((t & 3u) * 4u);  // STRIDE % 4 == 0: same mask all iters

    int  ci[DEPTH];
    int4 w [DEPTH];

    // Prologue: fill pipeline for iterations 0..PF-1.
    #pragma unroll
    for (int i = 0; i < PF; i++) {
        unsigned g = (t + (unsigned)i * STRIDE) >> 2;
        ci[i] = __ldcs(coeff_idx + g);
        w [i] = __ldcs(bvr + g);
    }
    float4 c_cur = __ldg(coeff_cache + ci[0]);  // gather for iteration 0

    #pragma unroll 4
    for (int i = 0; i < ITER; i++) {
        // Prefetch idx+bvr for iteration i+PF (clamped tail -> cache-hit reloads).
        int ipf = i + PF; if (ipf > ITER - 1) ipf = ITER - 1;
        unsigned gpf = (t + (unsigned)ipf * STRIDE) >> 2;
        ci[ipf & (DEPTH - 1)] = __ldcs(coeff_idx + gpf);
        w [ipf & (DEPTH - 1)] = __ldcs(bvr + gpf);

        // Issue gather for iteration i+1.
        int inx = i + 1; if (inx > ITER - 1) inx = ITER - 1;
        float4 c_nxt = __ldg(coeff_cache + ci[inx & (DEPTH - 1)]);

        // Decode + store iteration i.
        float4 r = decode_quarter(w[i & (DEPTH - 1)], c_cur, m0);
        __stcs(out + (t + (unsigned)i * STRIDE), r);

        c_cur = c_nxt;
    }
}

extern "C" void kernel_launch(void* const* d_in, const int* in_sizes, int n_in,
                              void* d_out, int out_size)
{
    const float4* coeff_cache = (const float4*)d_in[0];  // [65536,4] f32
    const int*    coeff_idx   = (const int*)d_in[1];     // [G] i32
    const int4*   bvr         = (const int4*)d_in[2];    // [G,4] i32
    float4*       out         = (float4*)d_out;          // [8192,8192] f32

    (void)in_sizes; (void)n_in; (void)out_size;

    unsigned blocks = NTHREADS / BLOCK;  // 4096
    sbvr_kernel<<<blocks, BLOCK>>>(coeff_cache, coeff_idx, bvr, out);
}

// round 5
// speedup vs baseline: 1.2937x; 1.2937x over previous
#include <cuda_runtime.h>
#include <cstdint>

// sbvr decode:
//   out[g*16 + l] = sum_s coeff_cache[coeff_idx[g]][s] * ((bvr[g][s] >> l) & 1)
// G = 4,194,304 groups, S = 4, L = 16.
//
// R4 -> R5: keep the software pipeline (it fixed latency: issue 34->70%),
// kill the overhead that made R4 issue-bound (118 warp-instr/quarter vs ~35
// of real work):
//  * block-contiguous tiling: per-iteration offsets are small compile-time
//    constants -> LDG/STG [Rbase+imm], zero steady-state addressing ops
//  * full unroll, static prologue/epilogue, no clamps, no rotation indices
//  * masks hoisted out of the decode asm (loop-invariant)

static constexpr unsigned QT_TOTAL = 16u * 1024u * 1024u;  // 4M groups * 4 quarters
static constexpr int      BLOCK    = 256;
static constexpr int      ITER     = 8;                    // quarter-groups per thread
static constexpr int      PF       = 3;                    // idx/bvr prefetch distance
static constexpr unsigned BLOCKS   = QT_TOTAL / (BLOCK * ITER);  // 8192
static constexpr int      GSTRIDE  = BLOCK / 4;            // 64 groups per iteration

// Pipe-balanced decode: lop3 with predicate output (ALU; AND+test in one op)
// feeding predicated add.f32 (FMA pipe). Exact fp32 -> rel_err 0.
__device__ __forceinline__ float4 decode_quarter(int4 w, float4 c,
                                                 unsigned m0, unsigned m1,
                                                 unsigned m2, unsigned m3)
{
    float4 r;
    asm(
    "{\n\t"
    ".reg .pred q, p0, p1, p2, p3;\n\t"
    ".reg .b32  t;\n\t"
    "setp.ne.u32 q, %4, %4;\n\t"
    // ---- element 0 ----
    "lop3.or.b32 t|p0, %4, %8, %4, 0xC0, q;\n\t"
    "lop3.or.b32 t|p1, %5, %8, %5, 0xC0, q;\n\t"
    "lop3.or.b32 t|p2, %6, %8, %6, 0xC0, q;\n\t"
    "lop3.or.b32 t|p3, %7, %8, %7, 0xC0, q;\n\t"
    "selp.f32 %0, %12, 0f00000000, p0;\n\t"
    "@p1 add.rn.f32 %0, %0, %13;\n\t"
    "@p2 add.rn.f32 %0, %0, %14;\n\t"
    "@p3 add.rn.f32 %0, %0, %15;\n\t"
    // ---- element 1 ----
    "lop3.or.b32 t|p0, %4, %9, %4, 0xC0, q;\n\t"
    "lop3.or.b32 t|p1, %5, %9, %5, 0xC0, q;\n\t"
    "lop3.or.b32 t|p2, %6, %9, %6, 0xC0, q;\n\t"
    "lop3.or.b32 t|p3, %7, %9, %7, 0xC0, q;\n\t"
    "selp.f32 %1, %12, 0f00000000, p0;\n\t"
    "@p1 add.rn.f32 %1, %1, %13;\n\t"
    "@p2 add.rn.f32 %1, %1, %14;\n\t"
    "@p3 add.rn.f32 %1, %1, %15;\n\t"
    // ---- element 2 ----
    "lop3.or.b32 t|p0, %4, %10, %4, 0xC0, q;\n\t"
    "lop3.or.b32 t|p1, %5, %10, %5, 0xC0, q;\n\t"
    "lop3.or.b32 t|p2, %6, %10, %6, 0xC0, q;\n\t"
    "lop3.or.b32 t|p3, %7, %10, %7, 0xC0, q;\n\t"
    "selp.f32 %2, %12, 0f00000000, p0;\n\t"
    "@p1 add.rn.f32 %2, %2, %13;\n\t"
    "@p2 add.rn.f32 %2, %2, %14;\n\t"
    "@p3 add.rn.f32 %2, %2, %15;\n\t"
    // ---- element 3 ----
    "lop3.or.b32 t|p0, %4, %11, %4, 0xC0, q;\n\t"
    "lop3.or.b32 t|p1, %5, %11, %5, 0xC0, q;\n\t"
    "lop3.or.b32 t|p2, %6, %11, %6, 0xC0, q;\n\t"
    "lop3.or.b32 t|p3, %7, %11, %7, 0xC0, q;\n\t"
    "selp.f32 %3, %12, 0f00000000, p0;\n\t"
    "@p1 add.rn.f32 %3, %3, %13;\n\t"
    "@p2 add.rn.f32 %3, %3, %14;\n\t"
    "@p3 add.rn.f32 %3, %3, %15;\n\t"
    "}\n\t"
    : "=f"(r.x), "=f"(r.y), "=f"(r.z), "=f"(r.w)
    : "r"(w.x), "r"(w.y), "r"(w.z), "r"(w.w),
      "r"(m0), "r"(m1), "r"(m2), "r"(m3),
      "f"(c.x), "f"(c.y), "f"(c.z), "f"(c.w));
    return r;
}

__global__ __launch_bounds__(BLOCK) void sbvr_kernel(
    const float4* __restrict__ coeff_cache,   // [65536] rows of 4 floats
    const int*    __restrict__ coeff_idx,     // [G]
    const int4*   __restrict__ bvr,           // [G]
    float4*       __restrict__ out)           // [4*G]
{
    // Block-contiguous tile: quarter-indices [b*BLOCK*ITER, ...), iteration i
    // at +i*BLOCK. All per-iteration offsets are small immediates.
    unsigned t = blockIdx.x * (unsigned)(BLOCK * ITER) + threadIdx.x;
    unsigned g = t >> 2;

    const int*  ip = coeff_idx + g;
    const int4* wp = bvr + g;
    float4*     op = out + t;

    unsigned m0 = 1u << ((t & 3u) * 4u);   // BLOCK % 4 == 0: invariant over i
    unsigned m1 = m0 << 1, m2 = m0 << 2, m3 = m0 << 3;

    int  ci[ITER];
    int4 w [ITER];

    // Prologue: idx+bvr for iterations 0..PF-1 (covers DRAM latency).
    #pragma unroll
    for (int i = 0; i < PF; i++) {
        ci[i] = __ldcs(ip + i * GSTRIDE);
        w [i] = __ldcs(wp + i * GSTRIDE);
    }
    float4 c_cur = __ldg(coeff_cache + ci[0]);  // gather for iteration 0

    #pragma unroll
    for (int i = 0; i < ITER; i++) {
        if (i + PF < ITER) {                    // static: no clamps
            ci[i + PF] = __ldcs(ip + (i + PF) * GSTRIDE);
            w [i + PF] = __ldcs(wp + (i + PF) * GSTRIDE);
        }
        float4 c_nxt = c_cur;
        if (i + 1 < ITER)                       // gather one iteration ahead
            c_nxt = __ldg(coeff_cache + ci[i + 1]);

        float4 r = decode_quarter(w[i], c_cur, m0, m1, m2, m3);
        __stcs(op + i * BLOCK, r);

        c_cur = c_nxt;
    }
}

extern "C" void kernel_launch(void* const* d_in, const int* in_sizes, int n_in,
                              void* d_out, int out_size)
{
    const float4* coeff_cache = (const float4*)d_in[0];  // [65536,4] f32
    const int*    coeff_idx   = (const int*)d_in[1];     // [G] i32
    const int4*   bvr         = (const int4*)d_in[2];    // [G,4] i32
    float4*       out         = (float4*)d_out;          // [8192,8192] f32

    (void)in_sizes; (void)n_in; (void)out_size;

    sbvr_kernel<<<BLOCKS, BLOCK>>>(coeff_cache, coeff_idx, bvr, out);
}

// round 6
// speedup vs baseline: 1.3271x; 1.0258x over previous
#include <cuda_runtime.h>
#include <cstdint>

// sbvr decode:
//   out[g*16 + l] = sum_s coeff_cache[coeff_idx[g]][s] * ((bvr[g][s] >> l) & 1)
// G = 4,194,304 groups, S = 4, L = 16.
//
// R5 -> R6: R5 profile: L1=69.8% (top), occ=54.7%, DRAM=61%. Limiter is the
// L1/LSU path (coeff gather = 8 scattered wavefronts/warp-iter) at too-low
// occupancy. Fix: force 6 blocks/SM (48 warps) via __launch_bounds__, and
// shrink live pipeline state (PF 3->2) so the reg cap (42) doesn't spill.
// Everything else (block-contiguous tiling, immediate-offset loads,
// pipe-balanced asm decode) unchanged from R5.

static constexpr unsigned QT_TOTAL = 16u * 1024u * 1024u;  // 4M groups * 4 quarters
static constexpr int      BLOCK    = 256;
static constexpr int      ITER     = 8;                    // quarter-groups per thread
static constexpr int      PF       = 2;                    // idx/bvr prefetch distance
static constexpr unsigned BLOCKS   = QT_TOTAL / (BLOCK * ITER);  // 8192
static constexpr int      GSTRIDE  = BLOCK / 4;            // 64 groups per iteration

// Pipe-balanced decode: lop3 with predicate output (ALU; AND+test in one op)
// feeding predicated add.f32 (FMA pipe). Exact fp32 -> rel_err 0.
__device__ __forceinline__ float4 decode_quarter(int4 w, float4 c,
                                                 unsigned m0, unsigned m1,
                                                 unsigned m2, unsigned m3)
{
    float4 r;
    asm(
    "{\n\t"
    ".reg .pred q, p0, p1, p2, p3;\n\t"
    ".reg .b32  t;\n\t"
    "setp.ne.u32 q, %4, %4;\n\t"
    // ---- element 0 ----
    "lop3.or.b32 t|p0, %4, %8, %4, 0xC0, q;\n\t"
    "lop3.or.b32 t|p1, %5, %8, %5, 0xC0, q;\n\t"
    "lop3.or.b32 t|p2, %6, %8, %6, 0xC0, q;\n\t"
    "lop3.or.b32 t|p3, %7, %8, %7, 0xC0, q;\n\t"
    "selp.f32 %0, %12, 0f00000000, p0;\n\t"
    "@p1 add.rn.f32 %0, %0, %13;\n\t"
    "@p2 add.rn.f32 %0, %0, %14;\n\t"
    "@p3 add.rn.f32 %0, %0, %15;\n\t"
    // ---- element 1 ----
    "lop3.or.b32 t|p0, %4, %9, %4, 0xC0, q;\n\t"
    "lop3.or.b32 t|p1, %5, %9, %5, 0xC0, q;\n\t"
    "lop3.or.b32 t|p2, %6, %9, %6, 0xC0, q;\n\t"
    "lop3.or.b32 t|p3, %7, %9, %7, 0xC0, q;\n\t"
    "selp.f32 %1, %12, 0f00000000, p0;\n\t"
    "@p1 add.rn.f32 %1, %1, %13;\n\t"
    "@p2 add.rn.f32 %1, %1, %14;\n\t"
    "@p3 add.rn.f32 %1, %1, %15;\n\t"
    // ---- element 2 ----
    "lop3.or.b32 t|p0, %4, %10, %4, 0xC0, q;\n\t"
    "lop3.or.b32 t|p1, %5, %10, %5, 0xC0, q;\n\t"
    "lop3.or.b32 t|p2, %6, %10, %6, 0xC0, q;\n\t"
    "lop3.or.b32 t|p3, %7, %10, %7, 0xC0, q;\n\t"
    "selp.f32 %2, %12, 0f00000000, p0;\n\t"
    "@p1 add.rn.f32 %2, %2, %13;\n\t"
    "@p2 add.rn.f32 %2, %2, %14;\n\t"
    "@p3 add.rn.f32 %2, %2, %15;\n\t"
    // ---- element 3 ----
    "lop3.or.b32 t|p0, %4, %11, %4, 0xC0, q;\n\t"
    "lop3.or.b32 t|p1, %5, %11, %5, 0xC0, q;\n\t"
    "lop3.or.b32 t|p2, %6, %11, %6, 0xC0, q;\n\t"
    "lop3.or.b32 t|p3, %7, %11, %7, 0xC0, q;\n\t"
    "selp.f32 %3, %12, 0f00000000, p0;\n\t"
    "@p1 add.rn.f32 %3, %3, %13;\n\t"
    "@p2 add.rn.f32 %3, %3, %14;\n\t"
    "@p3 add.rn.f32 %3, %3, %15;\n\t"
    "}\n\t"
    : "=f"(r.x), "=f"(r.y), "=f"(r.z), "=f"(r.w)
    : "r"(w.x), "r"(w.y), "r"(w.z), "r"(w.w),
      "r"(m0), "r"(m1), "r"(m2), "r"(m3),
      "f"(c.x), "f"(c.y), "f"(c.z), "f"(c.w));
    return r;
}

__global__ __launch_bounds__(BLOCK, 6) void sbvr_kernel(
    const float4* __restrict__ coeff_cache,   // [65536] rows of 4 floats
    const int*    __restrict__ coeff_idx,     // [G]
    const int4*   __restrict__ bvr,           // [G]
    float4*       __restrict__ out)           // [4*G]
{
    // Block-contiguous tile: quarter-indices [b*BLOCK*ITER, ...), iteration i
    // at +i*BLOCK. All per-iteration offsets are small immediates.
    unsigned t = blockIdx.x * (unsigned)(BLOCK * ITER) + threadIdx.x;
    unsigned g = t >> 2;

    const int*  ip = coeff_idx + g;
    const int4* wp = bvr + g;
    float4*     op = out + t;

    unsigned m0 = 1u << ((t & 3u) * 4u);   // BLOCK % 4 == 0: invariant over i
    unsigned m1 = m0 << 1, m2 = m0 << 2, m3 = m0 << 3;

    int  ci[ITER];
    int4 w [ITER];

    // Prologue: idx+bvr for iterations 0..PF-1.
    #pragma unroll
    for (int i = 0; i < PF; i++) {
        ci[i] = __ldcs(ip + i * GSTRIDE);
        w [i] = __ldcs(wp + i * GSTRIDE);
    }
    float4 c_cur = __ldg(coeff_cache + ci[0]);  // gather for iteration 0

    #pragma unroll
    for (int i = 0; i < ITER; i++) {
        if (i + PF < ITER) {                    // static: no clamps
            ci[i + PF] = __ldcs(ip + (i + PF) * GSTRIDE);
            w [i + PF] = __ldcs(wp + (i + PF) * GSTRIDE);
        }
        float4 c_nxt = c_cur;
        if (i + 1 < ITER)                       // gather one iteration ahead
            c_nxt = __ldg(coeff_cache + ci[i + 1]);

        float4 r = decode_quarter(w[i], c_cur, m0, m1, m2, m3);
        __stcs(op + i * BLOCK, r);

        c_cur = c_nxt;
    }
}

extern "C" void kernel_launch(void* const* d_in, const int* in_sizes, int n_in,
                              void* d_out, int out_size)
{
    const float4* coeff_cache = (const float4*)d_in[0];  // [65536,4] f32
    const int*    coeff_idx   = (const int*)d_in[1];     // [G] i32
    const int4*   bvr         = (const int4*)d_in[2];    // [G,4] i32
    float4*       out         = (float4*)d_out;          // [8192,8192] f32

    (void)in_sizes; (void)n_in; (void)out_size;

    sbvr_kernel<<<BLOCKS, BLOCK>>>(coeff_cache, coeff_idx, bvr, out);
}